// round 4
// baseline (speedup 1.0000x reference)
#include <cuda_runtime.h>
#include <math.h>
#include <stdint.h>

// Problem dims (fixed by the dataset)
#define B_    2
#define L_    1024
#define DM    1024
#define DI    2048
#define NS    16
#define DTR   64
#define DC    4
#define NTOK  (B_ * L_)      // 2048 tokens
#define XDBLW 96             // DT_RANK + 2*N

// ---------------------------------------------------------------------------
// Scratch (static __device__ arrays -- allocation-free per harness rules)
// ---------------------------------------------------------------------------
__device__ float g_xz   [(size_t)NTOK * 2 * DI];  // (B,L,2*DI)
__device__ float g_xconv[(size_t)NTOK * DI];      // conv+silu
__device__ float g_xdbl [(size_t)NTOK * XDBLW];   // dt|B|C
__device__ float g_delta[(size_t)NTOK * DI];      // softplus
__device__ float g_ybuf [(size_t)NTOK * DI];      // scan out

// ---------------------------------------------------------------------------
// Helpers
// ---------------------------------------------------------------------------
__device__ __forceinline__ float silu_f(float x) {
    return x / (1.0f + __expf(-x));
}
__device__ __forceinline__ float softplus_f(float x) {
    return (x > 20.0f) ? x : log1pf(__expf(x));
}
__device__ __forceinline__ float f2tf32f(float f) {
    uint32_t u;
    asm("cvt.rna.tf32.f32 %0, %1;\n" : "=r"(u) : "f"(f));
    return __uint_as_float(u);
}
__device__ __forceinline__ void mma_tf32(float* c,
                                         uint32_t a0, uint32_t a1, uint32_t a2, uint32_t a3,
                                         uint32_t b0, uint32_t b1) {
    asm volatile(
        "mma.sync.aligned.m16n8k8.row.col.f32.tf32.tf32.f32 "
        "{%0,%1,%2,%3}, {%4,%5,%6,%7}, {%8,%9}, {%0,%1,%2,%3};\n"
        : "+f"(c[0]), "+f"(c[1]), "+f"(c[2]), "+f"(c[3])
        : "r"(a0), "r"(a1), "r"(a2), "r"(a3), "r"(b0), "r"(b1));
}

// ---------------------------------------------------------------------------
// TF32 tensor-core GEMM: C[M,N] = A[M,K] @ B[K,N], all row-major fp32.
// Block tile 128x128, BK=16, 256 threads (8 warps; warp tile 64x32).
// A staged in smem with k-permutation k' = 4*(k&3) + (k>>2)  ->  each
// thread's 4 fragment values are contiguous (one LDS.128, conflict-free).
// tf32 conversion happens once at staging. Register double-buffered.
// Requires: M,N multiples of 128; K multiple of 16.
// EPI: 0 = plain store, 1 = softplus(acc + bias[col])
// ---------------------------------------------------------------------------
template <int EPI>
__global__ void __launch_bounds__(256, 2)
tgemm(const float* __restrict__ A, const float* __restrict__ Bm,
      float* __restrict__ C, int M, int N, int K,
      int lda, int ldb, int ldc, const float* __restrict__ bias)
{
    __shared__ float As[2][128][16];    // [m][k'] permuted, conflict-free LDS.128
    __shared__ float Bs[2][16][136];    // [k][n] padded, conflict-free scalar LDS

    const int tid  = threadIdx.x;
    const int bm   = blockIdx.y * 128;
    const int bn   = blockIdx.x * 128;
    const int lane = tid & 31;
    const int wid  = tid >> 5;
    const int wm   = (wid & 1) * 64;     // warp row offset
    const int wn   = (wid >> 1) * 32;    // warp col offset
    const int g    = lane >> 2;          // 0..7
    const int t    = lane & 3;           // 0..3

    // staging maps
    const int ar  = tid >> 2;            // A row 0..63 (and +64)
    const int at  = tid & 3;             // strided-k group
    const int bk  = tid >> 4;            // B k row 0..15
    const int bn4 = (tid & 15) * 4;      // B col chunk (and +64)

    const float* Ap0 = A + (size_t)(bm + ar) * lda + at;
    const float* Ap1 = A + (size_t)(bm + ar + 64) * lda + at;
    const float* Bp  = Bm + (size_t)bk * ldb + bn + bn4;

    float  areg[8];
    float4 breg[2];

    float acc[4][4][4];
    #pragma unroll
    for (int mi = 0; mi < 4; mi++)
        #pragma unroll
        for (int ni = 0; ni < 4; ni++)
            #pragma unroll
            for (int r = 0; r < 4; r++) acc[mi][ni][r] = 0.0f;

    const int nIter = K / 16;

    // ---- staging helpers (macros keep everything in registers) ----
#define LDG_TILE(kk)                                                        \
    {                                                                       \
        _Pragma("unroll")                                                   \
        for (int j = 0; j < 4; j++) {                                       \
            areg[j]     = Ap0[(kk) + 4 * j];                                \
            areg[4 + j] = Ap1[(kk) + 4 * j];                                \
        }                                                                   \
        breg[0] = *(const float4*)(Bp + (size_t)(kk) * ldb);                \
        breg[1] = *(const float4*)(Bp + (size_t)(kk) * ldb + 64);           \
    }

#define STS_TILE(bf)                                                        \
    {                                                                       \
        float4 v0 = make_float4(f2tf32f(areg[0]), f2tf32f(areg[1]),         \
                                f2tf32f(areg[2]), f2tf32f(areg[3]));        \
        float4 v1 = make_float4(f2tf32f(areg[4]), f2tf32f(areg[5]),         \
                                f2tf32f(areg[6]), f2tf32f(areg[7]));        \
        *(float4*)&As[bf][ar][4 * at]      = v0;                            \
        *(float4*)&As[bf][ar + 64][4 * at] = v1;                            \
        float4 w0 = make_float4(f2tf32f(breg[0].x), f2tf32f(breg[0].y),     \
                                f2tf32f(breg[0].z), f2tf32f(breg[0].w));    \
        float4 w1 = make_float4(f2tf32f(breg[1].x), f2tf32f(breg[1].y),     \
                                f2tf32f(breg[1].z), f2tf32f(breg[1].w));    \
        *(float4*)&Bs[bf][bk][bn4]      = w0;                               \
        *(float4*)&Bs[bf][bk][bn4 + 64] = w1;                               \
    }

    // prologue: tile 0 -> buf 0
    LDG_TILE(0);
    STS_TILE(0);
    __syncthreads();

    int buf = 0;
    for (int it = 0; it < nIter; ++it) {
        if (it + 1 < nIter) LDG_TILE((it + 1) * 16);

        // A fragments: one LDS.128 per row covers k = t, t+4, t+8, t+12
        uint4 av[4][2];
        #pragma unroll
        for (int mi = 0; mi < 4; mi++) {
            const int m0 = wm + mi * 16;
            av[mi][0] = *(const uint4*)&As[buf][m0 + g][4 * t];
            av[mi][1] = *(const uint4*)&As[buf][m0 + g + 8][4 * t];
        }

        #pragma unroll
        for (int s = 0; s < 2; s++) {
            uint32_t b0[4], b1[4];
            #pragma unroll
            for (int ni = 0; ni < 4; ni++) {
                const int n0 = wn + ni * 8 + g;
                b0[ni] = __float_as_uint(Bs[buf][s * 8 + t][n0]);
                b1[ni] = __float_as_uint(Bs[buf][s * 8 + t + 4][n0]);
            }
            #pragma unroll
            for (int mi = 0; mi < 4; mi++) {
                const uint32_t a0 = (s == 0) ? av[mi][0].x : av[mi][0].z;
                const uint32_t a1 = (s == 0) ? av[mi][1].x : av[mi][1].z;
                const uint32_t a2 = (s == 0) ? av[mi][0].y : av[mi][0].w;
                const uint32_t a3 = (s == 0) ? av[mi][1].y : av[mi][1].w;
                #pragma unroll
                for (int ni = 0; ni < 4; ni++)
                    mma_tf32(acc[mi][ni], a0, a1, a2, a3, b0[ni], b1[ni]);
            }
        }

        if (it + 1 < nIter) {
            STS_TILE(buf ^ 1);
            __syncthreads();
            buf ^= 1;
        }
    }

    // epilogue
    #pragma unroll
    for (int mi = 0; mi < 4; mi++) {
        #pragma unroll
        for (int ni = 0; ni < 4; ni++) {
            const int row = bm + wm + mi * 16 + g;
            const int col = bn + wn + ni * 8 + 2 * t;
            float v0 = acc[mi][ni][0], v1 = acc[mi][ni][1];
            float v2 = acc[mi][ni][2], v3 = acc[mi][ni][3];
            if (EPI == 1) {
                const float c0 = bias[col], c1 = bias[col + 1];
                v0 = softplus_f(v0 + c0);
                v1 = softplus_f(v1 + c1);
                v2 = softplus_f(v2 + c0);
                v3 = softplus_f(v3 + c1);
            }
            *(float2*)(C + (size_t)row * ldc + col)       = make_float2(v0, v1);
            *(float2*)(C + (size_t)(row + 8) * ldc + col) = make_float2(v2, v3);
        }
    }
#undef LDG_TILE
#undef STS_TILE
}

// ---------------------------------------------------------------------------
// Causal depthwise conv (k=4) + SiLU on the x half of xz
// ---------------------------------------------------------------------------
__global__ void conv_silu_kernel(const float* __restrict__ xz,
                                 const float* __restrict__ kw,   // (4, DI)
                                 const float* __restrict__ kb,   // (DI,)
                                 float* __restrict__ out)        // (NTOK, DI)
{
    int idx = blockIdx.x * blockDim.x + threadIdx.x;
    if (idx >= NTOK * DI) return;
    int d = idx & (DI - 1);
    int t = idx >> 11;           // token index b*L + l
    int l = t & (L_ - 1);

    float acc = kb[d];
    #pragma unroll
    for (int i = 0; i < DC; i++) {
        int ls = l - (DC - 1) + i;
        if (ls >= 0)
            acc = fmaf(xz[(size_t)(t - (DC - 1) + i) * (2 * DI) + d],
                       kw[i * DI + d], acc);
    }
    out[idx] = silu_f(acc);
}

// ---------------------------------------------------------------------------
// x_dbl = xconv @ Wx   (NTOK x 96, K=2048). 4 token rows per block to
// amortize Wx streaming through L2; 4 independent FMA chains.
// ---------------------------------------------------------------------------
#define XR 4
__global__ void __launch_bounds__(96)
xdbl_kernel(const float* __restrict__ xc, const float* __restrict__ Wx,
            float* __restrict__ out)
{
    __shared__ float sh[XR][DI];
    const int row0 = blockIdx.x * XR;
    const int col  = threadIdx.x;   // 0..95
    for (int i = col; i < XR * DI; i += 96)
        ((float*)sh)[i] = xc[(size_t)row0 * DI + i];
    __syncthreads();

    float acc[XR] = {0.0f, 0.0f, 0.0f, 0.0f};
    for (int k = 0; k < DI; k++) {
        float w = Wx[(size_t)k * XDBLW + col];
        #pragma unroll
        for (int r = 0; r < XR; r++)
            acc[r] = fmaf(sh[r][k], w, acc[r]);
    }
    #pragma unroll
    for (int r = 0; r < XR; r++)
        out[(size_t)(row0 + r) * XDBLW + col] = acc[r];
}

// ---------------------------------------------------------------------------
// Selective scan. One thread per (channel, state-n); 16-lane groups reduce y.
// Output: ybuf = (scan_y + u*Dskip) * silu(z)
// ---------------------------------------------------------------------------
__global__ void __launch_bounds__(256)
scan_kernel(const float* __restrict__ delta, const float* __restrict__ u,
            const float* __restrict__ xdbl,  const float* __restrict__ xz,
            const float* __restrict__ A_log, const float* __restrict__ Dskip,
            float* __restrict__ y)
{
    const int tid = threadIdx.x;
    const int grp = tid >> 4;                 // channel group within block
    const int n   = tid & 15;                 // state index
    const int c   = blockIdx.x * 16 + grp;    // global channel 0..B*DI-1
    const int b   = c >> 11;                  // / DI
    const int d   = c & (DI - 1);

    const float An = -__expf(A_log[d * NS + n]);
    const float Dd = Dskip[d];

    const float* drow = delta + (size_t)b * L_ * DI + d;
    const float* urow = u     + (size_t)b * L_ * DI + d;
    const float* zrow = xz    + (size_t)b * L_ * (2 * DI) + DI + d;
    const float* brow = xdbl  + (size_t)b * L_ * XDBLW + DTR + n;
    float*       yrow = y     + (size_t)b * L_ * DI + d;

    float x = 0.0f;
    for (int l = 0; l < L_; ++l) {
        float dv = drow[(size_t)l * DI];
        float uv = urow[(size_t)l * DI];
        float Bn = brow[(size_t)l * XDBLW];
        float Cn = brow[(size_t)l * XDBLW + NS];

        float dA = __expf(dv * An);
        x = fmaf(dA, x, dv * Bn * uv);

        float v = x * Cn;
        v += __shfl_xor_sync(0xffffffffu, v, 1, 16);
        v += __shfl_xor_sync(0xffffffffu, v, 2, 16);
        v += __shfl_xor_sync(0xffffffffu, v, 4, 16);
        v += __shfl_xor_sync(0xffffffffu, v, 8, 16);

        if (n == 0) {
            float zv = zrow[(size_t)l * (2 * DI)];
            yrow[(size_t)l * DI] = (v + uv * Dd) * silu_f(zv);
        }
    }
}

// ---------------------------------------------------------------------------
// Launch
// ---------------------------------------------------------------------------
extern "C" void kernel_launch(void* const* d_in, const int* in_sizes, int n_in,
                              void* d_out, int out_size)
{
    const float* hs      = (const float*)d_in[0];  // (B,L,DM)
    const float* Win     = (const float*)d_in[1];  // (DM, 2*DI)
    const float* Wx      = (const float*)d_in[2];  // (DI, 96)
    const float* Wdt     = (const float*)d_in[3];  // (DTR, DI)
    const float* dt_bias = (const float*)d_in[4];  // (DI,)
    const float* Wout    = (const float*)d_in[5];  // (DI, DM)
    const float* dwk     = (const float*)d_in[6];  // (4, DI)
    const float* dwb     = (const float*)d_in[7];  // (DI,)
    const float* A_log   = (const float*)d_in[8];  // (DI, NS)
    const float* Dskip   = (const float*)d_in[9];  // (DI,)
    float* out = (float*)d_out;

    float *xz, *xc, *xd, *dl, *yb;
    cudaGetSymbolAddress((void**)&xz, g_xz);
    cudaGetSymbolAddress((void**)&xc, g_xconv);
    cudaGetSymbolAddress((void**)&xd, g_xdbl);
    cudaGetSymbolAddress((void**)&dl, g_delta);
    cudaGetSymbolAddress((void**)&yb, g_ybuf);

    // 1) xz = hidden @ Win            (2048 x 4096, K=1024)   TF32 tensor cores
    tgemm<0><<<dim3(4096 / 128, 2048 / 128), 256>>>(
        hs, Win, xz, NTOK, 2 * DI, DM, DM, 2 * DI, 2 * DI, nullptr);

    // 2) depthwise causal conv + silu on x half
    conv_silu_kernel<<<(NTOK * DI + 255) / 256, 256>>>(xz, dwk, dwb, xc);

    // 3) x_dbl = xconv @ Wx           (2048 x 96, K=2048)     fp32 (small N)
    xdbl_kernel<<<NTOK / XR, 96>>>(xc, Wx, xd);

    // 4) delta = softplus(dt @ Wdt + dt_bias)   (2048 x 2048, K=64)  TF32
    tgemm<1><<<dim3(2048 / 128, 2048 / 128), 256>>>(
        xd, Wdt, dl, NTOK, DI, DTR, XDBLW, DI, DI, dt_bias);

    // 5) selective scan (+skip, *silu(z))
    scan_kernel<<<(B_ * DI) / 16, 256>>>(dl, xc, xd, xz, A_log, Dskip, yb);

    // 6) out = y @ Wout               (2048 x 1024, K=2048)   TF32
    tgemm<0><<<dim3(1024 / 128, 2048 / 128), 256>>>(
        yb, Wout, out, NTOK, DM, DI, DI, DM, DM, nullptr);
}